// round 4
// baseline (speedup 1.0000x reference)
#include <cuda_runtime.h>

// XdGate on site INDEX=3 of an L=8 qutrit (D=3) state vector, N = 3^8 = 6561.
//
// U = I x I x I x M x I x I x I x I with M|i> = |(3-i) mod 3> — a pure
// permutation of the site-3 trit (stride 3^4 = 81):
//   t=0 -> delta 0, t=1 -> +81, t=2 -> -81 (element offsets).
//
// Launch-overhead bound (~5us graph-replay floor; DRAM 0.1%, issue ~3%).
// R4: blockDim = 243 = 3*81 means the block base (blockIdx*243) is a multiple
// of 3*STRIDE, so the site-3 trit is t = threadIdx.x / 81 — no full-width
// div/mod chain. Exact grid cover 27 x 243 = 6561, no bounds guard.

static constexpr int STRIDE = 81;   // 3^4

__global__ __launch_bounds__(243) void xd_gate_kernel(
    const float* __restrict__ x, float* __restrict__ out) {
    int tid = threadIdx.x;                 // 0..242
    int t = tid / STRIDE;                  // site-3 trit: 0,1,2 (compile-time recip)
    int d = (t == 1) - (t == 2);           // 0 -> 0, 1 -> +1, 2 -> -1
    int idx = blockIdx.x * 243 + tid;      // exact cover of [0, 6561)
    out[idx] = x[idx + d * STRIDE];
}

extern "C" void kernel_launch(void* const* d_in, const int* in_sizes, int n_in,
                              void* d_out, int out_size) {
    const float* x = (const float*)d_in[0];   // [6561, 1] float32
    // d_in[1] is M [3,3] — permutation baked in.
    float* out = (float*)d_out;

    xd_gate_kernel<<<27, 243>>>(x, out);      // 27 * 243 = 6561 exactly
}